// round 9
// baseline (speedup 1.0000x reference)
#include <cuda_runtime.h>
#include <cstdint>

typedef unsigned long long u64;

#define KOUT    512
#define BMAX    512
#define CAP     2048
#define NB      4096
#define SSMP    1024
#define SORTMAX 1024
#define SLICES  8
#define NT1     256
#define NT2     512

__device__ u64      g_buf[BMAX * CAP];   // candidate scratch (8 MB)
__device__ unsigned g_cnt[BMAX];
__device__ float    g_hi[BMAX];

__device__ __forceinline__ unsigned fkey(float f) {
    unsigned u = __float_as_uint(f);
    return u ^ ((u & 0x80000000u) ? 0xFFFFFFFFu : 0x80000000u);
}
__device__ __forceinline__ float finv(unsigned v) {
    unsigned u = v ^ ((v & 0x80000000u) ? 0x80000000u : 0xFFFFFFFFu);
    return __uint_as_float(u);
}
__device__ __forceinline__ u64 pack(float x, float y) {
    return ((u64)fkey(x) << 32) | (u64)fkey(y);
}

// ---------- block-wide pivot search over hist[NB] ----------
template <int NTH>
__device__ void find_pivot(int* hist, int target, int* wsum,
                           int* s_pivot, int* s_below) {
    const int t = threadIdx.x;
    const int BPT = NB / NTH;
    const int base = t * BPT;
    int local = 0;
#pragma unroll
    for (int j = 0; j < BPT; j++) local += hist[base + j];
    const int lane = t & 31, warp = t >> 5;
    int incl = local;
#pragma unroll
    for (int o = 1; o < 32; o <<= 1) {
        int v = __shfl_up_sync(0xFFFFFFFFu, incl, o);
        if (lane >= o) incl += v;
    }
    if (lane == 31) wsum[warp] = incl;
    __syncthreads();
    if (t == 0) {
        int acc = 0;
#pragma unroll
        for (int i = 0; i < NTH / 32; i++) { int v = wsum[i]; wsum[i] = acc; acc += v; }
    }
    __syncthreads();
    const int excl = wsum[warp] + incl - local;
    if (excl < target && excl + local >= target) {
        int c = excl;
#pragma unroll
        for (int j = 0; j < BPT; j++) {
            int h = hist[base + j];
            if (c + h >= target) { *s_pivot = base + j; *s_below = c; break; }
            c += h;
        }
    }
    __syncthreads();
}

// ================= kernel 0: per-batch sample threshold =================
__global__ __launch_bounds__(NT1)
void sample_kernel(const float2* __restrict__ corners,
                   const int* __restrict__ lengths, int M) {
    __shared__ int hist[NB];
    __shared__ int wsum[NT1 / 32];
    __shared__ int s_pivot, s_below;
    const int b = blockIdx.x, t = threadIdx.x;
    const int n = lengths[b];
    const int kk = n < KOUT ? n : KOUT;

    if (t == 0) g_cnt[b] = 0;
    if (n <= CAP) {                       // everything fits: accept all
        if (t == 0) g_hi[b] = __int_as_float(0x7F800000);
        return;
    }
    const float2* base = corners + (size_t)b * M;
    for (int i = t; i < NB; i += NT1) hist[i] = 0;
    __syncthreads();
#pragma unroll
    for (int j = 0; j < SSMP / NT1; j++) {
        int s = t + j * NT1;
        int pos = (int)(((u64)s * (unsigned)n) >> 10);
        atomicAdd(&hist[fkey(base[pos].x) >> 20], 1);
    }
    __syncthreads();
    float q = (float)kk / (float)n;
    float m = (float)SSMP * q;
    int ts = (int)(m + 3.0f * sqrtf(m * (1.0f - q)) + 16.5f);
    if (ts < 1) ts = 1;
    if (ts > SSMP) ts = SSMP;
    find_pivot<NT1>(hist, ts, wsum, &s_pivot, &s_below);
    if (t == 0) {
        unsigned p = (unsigned)s_pivot;
        g_hi[b] = (p >= 4095u) ? __int_as_float(0x7F800000)
                               : finv(((p + 1u) << 20) - 1u);
    }
}

// ================= kernel 1: sliced filtered scan =================
__global__ __launch_bounds__(NT1)
void scan_kernel(const float2* __restrict__ corners,
                 const int* __restrict__ lengths, int M) {
    const int b = blockIdx.y, s = blockIdx.x, t = threadIdx.x;
    const int n = lengths[b];
    if (n == 0) return;
    const float hi = g_hi[b];
    int n8 = ((n + SLICES - 1) / SLICES + 1) & ~1;   // even slice size
    int lo = s * n8;
    int end = lo + n8 < n ? lo + n8 : n;
    if (lo >= end) return;
    const float2* base = corners + (size_t)b * M;
    u64* gb = g_buf + (size_t)b * CAP;
    unsigned* gc = &g_cnt[b];

    int i = lo + 2 * t;
    for (; i + 2 * NT1 + 1 < end; i += 4 * NT1) {
        float4 a = *(const float4*)(base + i);
        float4 c = *(const float4*)(base + i + 2 * NT1);
        bool p0 = a.x <= hi, p1 = a.z <= hi, p2 = c.x <= hi, p3 = c.z <= hi;
        if (__any_sync(0xFFFFFFFFu, p0 | p1 | p2 | p3)) {
            int cnt4 = (int)p0 + (int)p1 + (int)p2 + (int)p3;
            int tot = cnt4;
#pragma unroll
            for (int o = 16; o > 0; o >>= 1) tot += __shfl_down_sync(0xFFFFFFFFu, tot, o);
            unsigned bse;
            if ((t & 31) == 0) bse = atomicAdd(gc, (unsigned)tot);
            bse = __shfl_sync(0xFFFFFFFFu, bse, 0);
            int pre = cnt4;
#pragma unroll
            for (int o = 1; o < 32; o <<= 1) {
                int v = __shfl_up_sync(0xFFFFFFFFu, pre, o);
                if ((t & 31) >= o) pre += v;
            }
            pre -= cnt4;
            unsigned pos = bse + (unsigned)pre;
            if (p0 && pos < CAP) gb[pos++] = pack(a.x, a.y);
            if (p1 && pos < CAP) gb[pos++] = pack(a.z, a.w);
            if (p2 && pos < CAP) gb[pos++] = pack(c.x, c.y);
            if (p3 && pos < CAP) gb[pos++] = pack(c.z, c.w);
        }
    }
    for (; i + 1 < end; i += 2 * NT1) {
        float4 a = *(const float4*)(base + i);
        if (a.x <= hi) { unsigned p = atomicAdd(gc, 1u); if (p < CAP) gb[p] = pack(a.x, a.y); }
        if (a.z <= hi) { unsigned p = atomicAdd(gc, 1u); if (p < CAP) gb[p] = pack(a.z, a.w); }
    }
    if (i < end) {
        float2 c = base[i];
        if (c.x <= hi) { unsigned p = atomicAdd(gc, 1u); if (p < CAP) gb[p] = pack(c.x, c.y); }
    }
}

// ================= kernel 2: select + sort + emit =================
struct Sh2 {
    u64 buf[CAP];
    union { int hist[NB]; u64 buf2[CAP]; };
    int wsum[NT2 / 32];
    int cnt, pivot, below;
};

__device__ void bitonic(u64* a, int P) {
    const int t = threadIdx.x;
    for (int size = 2; size <= P; size <<= 1)
        for (int stride = size >> 1; stride > 0; stride >>= 1) {
            for (int i = t; i < P; i += NT2) {
                int j = i ^ stride;
                if (j > i) {
                    u64 x = a[i], y = a[j];
                    bool up = ((i & size) == 0);
                    if ((x > y) == up) { a[i] = y; a[j] = x; }
                }
            }
            __syncthreads();
        }
}

__global__ __launch_bounds__(NT2)
void sort_kernel(const float2* __restrict__ corners,
                 const int* __restrict__ lengths,
                 float2* __restrict__ out, int M) {
    __shared__ Sh2 sh;
    const int b = blockIdx.x, t = threadIdx.x;
    const int n = lengths[b];
    const int kk = n < KOUT ? n : KOUT;
    float2* outp = out + (size_t)b * KOUT;
    if (kk == 0) { outp[t] = make_float2(0.f, 0.f); return; }
    const float2* base = corners + (size_t)b * M;

    unsigned rawc = g_cnt[b];
    int C;
    if (rawc >= (unsigned)kk && rawc <= CAP) {
        C = (int)rawc;
        for (int i = t; i < C; i += NT2) sh.buf[i] = g_buf[(size_t)b * CAP + i];
        __syncthreads();
    } else {
        // ---- exact fallback: 3-level histogram on x over full batch ----
        for (int i = t; i < NB; i += NT2) sh.hist[i] = 0;
        __syncthreads();
        for (int i = t; i < n; i += NT2) atomicAdd(&sh.hist[fkey(base[i].x) >> 20], 1);
        __syncthreads();
        find_pivot<NT2>(sh.hist, kk, sh.wsum, &sh.pivot, &sh.below);
        int d0 = sh.pivot, below0 = sh.below, in0 = sh.hist[d0];
        unsigned T;
        if (below0 + in0 <= CAP) T = ((unsigned)d0 << 20) | 0xFFFFFu;
        else {
            __syncthreads();
            for (int i = t; i < NB; i += NT2) sh.hist[i] = 0;
            __syncthreads();
            for (int i = t; i < n; i += NT2) {
                unsigned u = fkey(base[i].x);
                if ((u >> 20) == (unsigned)d0) atomicAdd(&sh.hist[(u >> 8) & 0xFFFu], 1);
            }
            __syncthreads();
            find_pivot<NT2>(sh.hist, kk - below0, sh.wsum, &sh.pivot, &sh.below);
            int d1 = sh.pivot, below1 = sh.below, in1 = sh.hist[d1];
            if (below0 + below1 + in1 <= CAP)
                T = ((unsigned)d0 << 20) | ((unsigned)d1 << 8) | 0xFFu;
            else {
                __syncthreads();
                for (int i = t; i < NB; i += NT2) sh.hist[i] = 0;
                __syncthreads();
                const unsigned pref = ((unsigned)d0 << 12) | (unsigned)d1;
                for (int i = t; i < n; i += NT2) {
                    unsigned u = fkey(base[i].x);
                    if ((u >> 8) == pref) atomicAdd(&sh.hist[u & 0xFFu], 1);
                }
                __syncthreads();
                find_pivot<NT2>(sh.hist, kk - below0 - below1, sh.wsum, &sh.pivot, &sh.below);
                T = ((unsigned)d0 << 20) | ((unsigned)d1 << 8) | (unsigned)sh.pivot;
            }
        }
        if (t == 0) sh.cnt = 0;
        __syncthreads();
        for (int i = t; i < n; i += NT2) {
            float2 c = base[i];
            if (fkey(c.x) <= T) {
                int pos = atomicAdd(&sh.cnt, 1);
                if (pos < CAP) sh.buf[pos] = pack(c.x, c.y);
            }
        }
        __syncthreads();
        C = sh.cnt < CAP ? sh.cnt : CAP;
    }

    u64* sbuf = sh.buf;
    // ---- selection: cut to <= SORTMAX before sorting ----
    if (C > SORTMAX) {
        for (int i = t; i < NB; i += NT2) sh.hist[i] = 0;
        __syncthreads();
        for (int i = t; i < C; i += NT2) atomicAdd(&sh.hist[(int)(sh.buf[i] >> 52)], 1);
        __syncthreads();
        find_pivot<NT2>(sh.hist, kk, sh.wsum, &sh.pivot, &sh.below);
        int p0 = sh.pivot, below0 = sh.below, in0 = sh.hist[p0];
        int keepN = below0 + in0;
        int p1 = 0; bool two = false;
        if (keepN > SORTMAX) {
            __syncthreads();
            for (int i = t; i < NB; i += NT2) sh.hist[i] = 0;
            __syncthreads();
            for (int i = t; i < C; i += NT2) {
                u64 k = sh.buf[i];
                if ((int)(k >> 52) == p0) atomicAdd(&sh.hist[(int)((k >> 40) & 0xFFFu)], 1);
            }
            __syncthreads();
            find_pivot<NT2>(sh.hist, kk - below0, sh.wsum, &sh.pivot, &sh.below);
            p1 = sh.pivot;
            keepN = below0 + sh.below + sh.hist[p1];
            two = true;
        }
        if (keepN <= SORTMAX) {
            if (t == 0) sh.cnt = 0;
            __syncthreads();
            for (int i = t; i < C; i += NT2) {
                u64 k = sh.buf[i];
                int hb = (int)(k >> 52);
                bool keep = two ? (hb < p0 || (hb == p0 && (int)((k >> 40) & 0xFFFu) <= p1))
                                : (hb <= p0);
                if (keep) { int pos = atomicAdd(&sh.cnt, 1); sh.buf2[pos] = k; }
            }
            __syncthreads();
            C = sh.cnt;
            sbuf = sh.buf2;
        }
    }

    int P = 1; while (P < C) P <<= 1;
    if (P < 2) P = 2;
    for (int i = C + t; i < P; i += NT2) sbuf[i] = ~0ull;
    __syncthreads();
    bitonic(sbuf, P);

    float2 o = make_float2(0.f, 0.f);
    if (t < kk) {
        u64 k = sbuf[t];
        o = make_float2(finv((unsigned)(k >> 32)), finv((unsigned)k));
    }
    outp[t] = o;
}

extern "C" void kernel_launch(void* const* d_in, const int* in_sizes, int n_in,
                              void* d_out, int out_size) {
    const float2* corners = (const float2*)d_in[0];
    const int*    lengths = (const int*)d_in[1];
    float2*       out     = (float2*)d_out;
    const int B = in_sizes[1];
    const int M = in_sizes[0] / (B * 2);
    sample_kernel<<<B, NT1>>>(corners, lengths, M);
    scan_kernel<<<dim3(SLICES, B), NT1>>>(corners, lengths, M);
    sort_kernel<<<B, NT2>>>(corners, lengths, out, M);
}

// round 10
// speedup vs baseline: 1.0833x; 1.0833x over previous
#include <cuda_runtime.h>
#include <cstdint>

typedef unsigned long long u64;

#define KOUT    512
#define BMAX    512
#define CAP     2048
#define NB      4096
#define SSMP    1024
#define SORTMAX 1024
#define SLICES  8
#define NT1     256
#define NT2     512

__device__ u64      g_buf[BMAX * CAP];   // candidate scratch (8 MB)
__device__ unsigned g_cnt[BMAX];
__device__ float    g_hi[BMAX];

__device__ __forceinline__ unsigned fkey(float f) {
    unsigned u = __float_as_uint(f);
    return u ^ ((u & 0x80000000u) ? 0xFFFFFFFFu : 0x80000000u);
}
__device__ __forceinline__ float finv(unsigned v) {
    unsigned u = v ^ ((v & 0x80000000u) ? 0x80000000u : 0xFFFFFFFFu);
    return __uint_as_float(u);
}
__device__ __forceinline__ u64 pack(float x, float y) {
    return ((u64)fkey(x) << 32) | (u64)fkey(y);
}

template <int NTH>
__device__ void find_pivot(int* hist, int target, int* wsum,
                           int* s_pivot, int* s_below) {
    const int t = threadIdx.x;
    const int BPT = NB / NTH;
    const int base = t * BPT;
    int local = 0;
#pragma unroll
    for (int j = 0; j < BPT; j++) local += hist[base + j];
    const int lane = t & 31, warp = t >> 5;
    int incl = local;
#pragma unroll
    for (int o = 1; o < 32; o <<= 1) {
        int v = __shfl_up_sync(0xFFFFFFFFu, incl, o);
        if (lane >= o) incl += v;
    }
    if (lane == 31) wsum[warp] = incl;
    __syncthreads();
    if (t == 0) {
        int acc = 0;
#pragma unroll
        for (int i = 0; i < NTH / 32; i++) { int v = wsum[i]; wsum[i] = acc; acc += v; }
    }
    __syncthreads();
    const int excl = wsum[warp] + incl - local;
    if (excl < target && excl + local >= target) {
        int c = excl;
#pragma unroll
        for (int j = 0; j < BPT; j++) {
            int h = hist[base + j];
            if (c + h >= target) { *s_pivot = base + j; *s_below = c; break; }
            c += h;
        }
    }
    __syncthreads();
}

// ================= kernel 0: per-batch sample threshold (chunked, coalesced) =================
__global__ __launch_bounds__(NT1)
void sample_kernel(const float2* __restrict__ corners,
                   const int* __restrict__ lengths, int M) {
    __shared__ int hist[NB];
    __shared__ int wsum[NT1 / 32];
    __shared__ int s_pivot, s_below;
    const int b = blockIdx.x, t = threadIdx.x;
    const int n = lengths[b];
    const int kk = n < KOUT ? n : KOUT;

    if (t == 0) g_cnt[b] = 0;
    if (n <= CAP) {
        if (t == 0) g_hi[b] = __int_as_float(0x7F800000);
        return;
    }
    const float2* base = corners + (size_t)b * M;
    for (int i = t; i < NB; i += NT1) hist[i] = 0;
    __syncthreads();
    // 8 chunks of 128 consecutive points, spread across [0, n)
#pragma unroll
    for (int j = 0; j < SSMP / NT1; j++) {
        int s = t + j * NT1;
        int chunk = s >> 7, off = s & 127;
        int pos = (int)((long long)chunk * (n - 128) / 7) + off;
        atomicAdd(&hist[fkey(base[pos].x) >> 20], 1);
    }
    __syncthreads();
    float q = (float)kk / (float)n;
    float m = (float)SSMP * q;
    int ts = (int)(m + 3.0f * sqrtf(m * (1.0f - q)) + 8.5f);
    if (ts < 1) ts = 1;
    if (ts > SSMP) ts = SSMP;
    find_pivot<NT1>(hist, ts, wsum, &s_pivot, &s_below);
    if (t == 0) {
        unsigned p = (unsigned)s_pivot;
        g_hi[b] = (p >= 4095u) ? __int_as_float(0x7F800000)
                               : finv(((p + 1u) << 20) - 1u);
    }
}

// ================= kernel 1: sliced filtered scan =================
__global__ __launch_bounds__(NT1)
void scan_kernel(const float2* __restrict__ corners,
                 const int* __restrict__ lengths, int M) {
    const int b = blockIdx.y, s = blockIdx.x, t = threadIdx.x;
    const int n = lengths[b];
    if (n == 0) return;
    const float hi = g_hi[b];
    int n8 = ((n + SLICES - 1) / SLICES + 1) & ~1;
    int lo = s * n8;
    int end = lo + n8 < n ? lo + n8 : n;
    if (lo >= end) return;
    const float2* base = corners + (size_t)b * M;
    u64* gb = g_buf + (size_t)b * CAP;
    unsigned* gc = &g_cnt[b];

    int i = lo + 2 * t;
    for (; i + 2 * NT1 + 1 < end; i += 4 * NT1) {
        float4 a = *(const float4*)(base + i);
        float4 c = *(const float4*)(base + i + 2 * NT1);
        bool p0 = a.x <= hi, p1 = a.z <= hi, p2 = c.x <= hi, p3 = c.z <= hi;
        if (__any_sync(0xFFFFFFFFu, p0 | p1 | p2 | p3)) {
            int cnt4 = (int)p0 + (int)p1 + (int)p2 + (int)p3;
            int tot = cnt4;
#pragma unroll
            for (int o = 16; o > 0; o >>= 1) tot += __shfl_down_sync(0xFFFFFFFFu, tot, o);
            unsigned bse;
            if ((t & 31) == 0) bse = atomicAdd(gc, (unsigned)tot);
            bse = __shfl_sync(0xFFFFFFFFu, bse, 0);
            int pre = cnt4;
#pragma unroll
            for (int o = 1; o < 32; o <<= 1) {
                int v = __shfl_up_sync(0xFFFFFFFFu, pre, o);
                if ((t & 31) >= o) pre += v;
            }
            pre -= cnt4;
            unsigned pos = bse + (unsigned)pre;
            if (p0 && pos < CAP) gb[pos++] = pack(a.x, a.y);
            if (p1 && pos < CAP) gb[pos++] = pack(a.z, a.w);
            if (p2 && pos < CAP) gb[pos++] = pack(c.x, c.y);
            if (p3 && pos < CAP) gb[pos++] = pack(c.z, c.w);
        }
    }
    for (; i + 1 < end; i += 2 * NT1) {
        float4 a = *(const float4*)(base + i);
        if (a.x <= hi) { unsigned p = atomicAdd(gc, 1u); if (p < CAP) gb[p] = pack(a.x, a.y); }
        if (a.z <= hi) { unsigned p = atomicAdd(gc, 1u); if (p < CAP) gb[p] = pack(a.z, a.w); }
    }
    if (i < end) {
        float2 c = base[i];
        if (c.x <= hi) { unsigned p = atomicAdd(gc, 1u); if (p < CAP) gb[p] = pack(c.x, c.y); }
    }
}

// ================= kernel 2: adaptive select + sort + emit =================
struct Sh2 {
    u64 buf[CAP];
    union { int hist[NB]; u64 buf2[CAP]; };
    int wsum[NT2 / 32];
    u64 mnw[NT2 / 32], mxw[NT2 / 32];
    u64 s_mn, s_mx;
    int cnt, pivot, below;
};

__device__ void bitonic(u64* a, int P) {
    const int t = threadIdx.x;
    for (int size = 2; size <= P; size <<= 1)
        for (int stride = size >> 1; stride > 0; stride >>= 1) {
            for (int i = t; i < P; i += NT2) {
                int j = i ^ stride;
                if (j > i) {
                    u64 x = a[i], y = a[j];
                    bool up = ((i & size) == 0);
                    if ((x > y) == up) { a[i] = y; a[j] = x; }
                }
            }
            __syncthreads();
        }
}

__global__ __launch_bounds__(NT2)
void sort_kernel(const float2* __restrict__ corners,
                 const int* __restrict__ lengths,
                 float2* __restrict__ out, int M) {
    __shared__ Sh2 sh;
    const int b = blockIdx.x, t = threadIdx.x;
    const int n = lengths[b];
    const int kk = n < KOUT ? n : KOUT;
    float2* outp = out + (size_t)b * KOUT;
    if (kk == 0) { outp[t] = make_float2(0.f, 0.f); return; }
    const float2* base = corners + (size_t)b * M;

    unsigned rawc = g_cnt[b];
    int C;
    if (rawc >= (unsigned)kk && rawc <= CAP) {
        C = (int)rawc;
        for (int i = t; i < C; i += NT2) sh.buf[i] = g_buf[(size_t)b * CAP + i];
        __syncthreads();
    } else {
        // exact fallback: 3-level histogram on x over full batch (rare)
        for (int i = t; i < NB; i += NT2) sh.hist[i] = 0;
        __syncthreads();
        for (int i = t; i < n; i += NT2) atomicAdd(&sh.hist[fkey(base[i].x) >> 20], 1);
        __syncthreads();
        find_pivot<NT2>(sh.hist, kk, sh.wsum, &sh.pivot, &sh.below);
        int d0 = sh.pivot, below0 = sh.below, in0 = sh.hist[d0];
        unsigned T;
        if (below0 + in0 <= CAP) T = ((unsigned)d0 << 20) | 0xFFFFFu;
        else {
            __syncthreads();
            for (int i = t; i < NB; i += NT2) sh.hist[i] = 0;
            __syncthreads();
            for (int i = t; i < n; i += NT2) {
                unsigned u = fkey(base[i].x);
                if ((u >> 20) == (unsigned)d0) atomicAdd(&sh.hist[(u >> 8) & 0xFFFu], 1);
            }
            __syncthreads();
            find_pivot<NT2>(sh.hist, kk - below0, sh.wsum, &sh.pivot, &sh.below);
            int d1 = sh.pivot, below1 = sh.below, in1 = sh.hist[d1];
            if (below0 + below1 + in1 <= CAP)
                T = ((unsigned)d0 << 20) | ((unsigned)d1 << 8) | 0xFFu;
            else {
                __syncthreads();
                for (int i = t; i < NB; i += NT2) sh.hist[i] = 0;
                __syncthreads();
                const unsigned pref = ((unsigned)d0 << 12) | (unsigned)d1;
                for (int i = t; i < n; i += NT2) {
                    unsigned u = fkey(base[i].x);
                    if ((u >> 8) == pref) atomicAdd(&sh.hist[u & 0xFFu], 1);
                }
                __syncthreads();
                find_pivot<NT2>(sh.hist, kk - below0 - below1, sh.wsum, &sh.pivot, &sh.below);
                T = ((unsigned)d0 << 20) | ((unsigned)d1 << 8) | (unsigned)sh.pivot;
            }
        }
        if (t == 0) sh.cnt = 0;
        __syncthreads();
        for (int i = t; i < n; i += NT2) {
            float2 c = base[i];
            if (fkey(c.x) <= T) {
                int pos = atomicAdd(&sh.cnt, 1);
                if (pos < CAP) sh.buf[pos] = pack(c.x, c.y);
            }
        }
        __syncthreads();
        C = sh.cnt < CAP ? sh.cnt : CAP;
    }

    u64* sbuf = sh.buf;
    // ---- adaptive-range selection: cut to <= SORTMAX (ideally exactly kk) ----
    if (C > SORTMAX) {
        // block min/max of keys
        u64 mn = ~0ull, mx = 0ull;
        for (int i = t; i < C; i += NT2) {
            u64 k = sh.buf[i];
            mn = k < mn ? k : mn;
            mx = k > mx ? k : mx;
        }
        const int lane = t & 31, warp = t >> 5;
#pragma unroll
        for (int o = 16; o > 0; o >>= 1) {
            u64 a = __shfl_down_sync(0xFFFFFFFFu, mn, o);
            u64 bx = __shfl_down_sync(0xFFFFFFFFu, mx, o);
            mn = a < mn ? a : mn;
            mx = bx > mx ? bx : mx;
        }
        if (lane == 0) { sh.mnw[warp] = mn; sh.mxw[warp] = mx; }
        __syncthreads();
        if (t == 0) {
            u64 m0 = ~0ull, m1 = 0ull;
            for (int i = 0; i < NT2 / 32; i++) {
                m0 = sh.mnw[i] < m0 ? sh.mnw[i] : m0;
                m1 = sh.mxw[i] > m1 ? sh.mxw[i] : m1;
            }
            sh.s_mn = m0; sh.s_mx = m1;
        }
        __syncthreads();
        const u64 kmn = sh.s_mn, kmx = sh.s_mx;
        if (kmn == kmx) {
            C = kk;                       // all keys identical: any kk of them
        } else {
            u64 range = kmx - kmn;
            int hb = 63 - __clzll(range);
            int shift = hb - 11; if (shift < 0) shift = 0;
            for (int i = t; i < NB; i += NT2) sh.hist[i] = 0;
            __syncthreads();
            for (int i = t; i < C; i += NT2)
                atomicAdd(&sh.hist[(int)((sh.buf[i] - kmn) >> shift)], 1);
            __syncthreads();
            find_pivot<NT2>(sh.hist, kk, sh.wsum, &sh.pivot, &sh.below);
            int p = sh.pivot, below = sh.below;
            int keepN = below + sh.hist[p];
            __syncthreads();              // hist reads done before buf2 writes
            if (keepN <= SORTMAX) {
                if (t == 0) sh.cnt = 0;
                __syncthreads();
                for (int i = t; i < C; i += NT2) {
                    u64 k = sh.buf[i];
                    if ((int)((k - kmn) >> shift) <= p) {
                        int pos = atomicAdd(&sh.cnt, 1);
                        sh.buf2[pos] = k;
                    }
                }
                __syncthreads();
                C = keepN;
                sbuf = sh.buf2;
            } else if (shift == 0) {
                // pivot bin is one exact key value: keep below-keys + copies
                if (t == 0) sh.cnt = 0;
                __syncthreads();
                for (int i = t; i < C; i += NT2) {
                    u64 k = sh.buf[i];
                    if ((int)(k - kmn) < p) {
                        int pos = atomicAdd(&sh.cnt, 1);
                        sh.buf2[pos] = k;
                    }
                }
                __syncthreads();
                u64 pkey = kmn + (u64)p;
                for (int i = below + t; i < kk; i += NT2) sh.buf2[i] = pkey;
                __syncthreads();
                C = kk;
                sbuf = sh.buf2;
            }
            // else: pathological — sort full buf (C <= CAP)
        }
    }

    int P = 1; while (P < C) P <<= 1;
    if (P < 2) P = 2;
    for (int i = C + t; i < P; i += NT2) sbuf[i] = ~0ull;
    __syncthreads();
    bitonic(sbuf, P);

    float2 o = make_float2(0.f, 0.f);
    if (t < kk) {
        u64 k = sbuf[t];
        o = make_float2(finv((unsigned)(k >> 32)), finv((unsigned)k));
    }
    outp[t] = o;
}

extern "C" void kernel_launch(void* const* d_in, const int* in_sizes, int n_in,
                              void* d_out, int out_size) {
    const float2* corners = (const float2*)d_in[0];
    const int*    lengths = (const int*)d_in[1];
    float2*       out     = (float2*)d_out;
    const int B = in_sizes[1];
    const int M = in_sizes[0] / (B * 2);
    sample_kernel<<<B, NT1>>>(corners, lengths, M);
    scan_kernel<<<dim3(SLICES, B), NT1>>>(corners, lengths, M);
    sort_kernel<<<B, NT2>>>(corners, lengths, out, M);
}